// round 1
// baseline (speedup 1.0000x reference)
#include <cuda_runtime.h>
#include <cstdint>

// FMLayer: out[b, p] = wdot[p] * x[b, j1(p)] * x[b, j2(p)]
//   N_FEATURES = 512, K = 4, BATCH = 1024
//   P = 512*511/2 = 130816 pairs (upper triangle, row-major by j1)
// Inputs (metadata order): d_in[0] = x [1024, 512] f32, d_in[1] = weight [512, 4] f32
// Output: [1024, 130816] f32  (535.8 MB -> DRAM-write-bound)

#define NF    512
#define KDIM  4
#define BATCH 1024
#define NPAIR 130816              // 512*511/2
#define NQ4   (NPAIR / 4)         // 32704 float4 slots per batch row

// Scratch (allocation-free rule: __device__ globals)
__device__ __align__(16) float g_wdot[NPAIR];
__device__ __align__(16) int   g_jidx[NPAIR];   // (j1 << 16) | j2

// offset(j1) = number of pairs before row j1 = 511*j1 - j1*(j1-1)/2
__device__ __forceinline__ int tri_offset(int j1) {
    return (NF - 1) * j1 - (j1 * (j1 - 1)) / 2;
}

__global__ void fm_setup_kernel(const float* __restrict__ w) {
    int p = blockIdx.x * blockDim.x + threadIdx.x;
    if (p >= NPAIR) return;

    // invert triangular index: largest j1 with tri_offset(j1) <= p
    // j1 = floor((2N-1 - sqrt((2N-1)^2 - 8p)) / 2), then integer fixup
    double disc = 1023.0 * 1023.0 - 8.0 * (double)p;
    int j1 = (int)((1023.0 - sqrt(disc)) * 0.5);
    if (j1 < 0) j1 = 0;
    while (j1 + 1 < NF && tri_offset(j1 + 1) <= p) j1++;
    while (j1 > 0 && tri_offset(j1) > p) j1--;
    int j2 = p - tri_offset(j1) + j1 + 1;

    // wdot = <w[j1,:], w[j2,:]>, K=4 -> one float4 per row
    const float4* w4 = reinterpret_cast<const float4*>(w);
    float4 a = __ldg(&w4[j1]);
    float4 b = __ldg(&w4[j2]);
    float wdot = a.x * b.x + a.y * b.y + a.z * b.z + a.w * b.w;

    g_wdot[p] = wdot;
    g_jidx[p] = (j1 << 16) | j2;
}

// Main kernel: one block = (one batch row) x (chunk of 2048 float4 = 8192 pairs)
// grid = (16, 1024), block = 256. Each thread: 8 coalesced float4 streaming stores.
__global__ void __launch_bounds__(256, 8) fm_main_kernel(
    const float* __restrict__ x, float* __restrict__ out)
{
    __shared__ float xs[NF];

    const int b = blockIdx.y;
    const float* xr = x + (size_t)b * NF;
    // stage x row (512 f32 = 2 KB) into shared
    #pragma unroll
    for (int i = threadIdx.x; i < NF; i += 256) xs[i] = xr[i];
    __syncthreads();

    const int4*   jid4 = reinterpret_cast<const int4*>(g_jidx);
    const float4* wd4  = reinterpret_cast<const float4*>(g_wdot);
    float4* out4 = reinterpret_cast<float4*>(out + (size_t)b * NPAIR);

    const int base4 = blockIdx.x * 2048;

    #pragma unroll
    for (int it = 0; it < 8; it++) {
        int q = base4 + it * 256 + threadIdx.x;
        if (q < NQ4) {
            int4   j  = jid4[q];   // L2-resident after first batch row
            float4 wd = wd4[q];
            float4 r;
            r.x = wd.x * xs[j.x >> 16] * xs[j.x & 0xffff];
            r.y = wd.y * xs[j.y >> 16] * xs[j.y & 0xffff];
            r.z = wd.z * xs[j.z >> 16] * xs[j.z & 0xffff];
            r.w = wd.w * xs[j.w >> 16] * xs[j.w & 0xffff];
            __stcs(&out4[q], r);   // streaming store: output never re-read
        }
    }
}

extern "C" void kernel_launch(void* const* d_in, const int* in_sizes, int n_in,
                              void* d_out, int out_size)
{
    const float* x = (const float*)d_in[0];   // [1024, 512]
    const float* w = (const float*)d_in[1];   // [512, 4]
    float* out = (float*)d_out;               // [1024, 130816]
    (void)in_sizes; (void)n_in; (void)out_size;

    fm_setup_kernel<<<(NPAIR + 255) / 256, 256>>>(w);

    dim3 grid(16, BATCH);   // 16 * 2048 f4 = 32768 >= 32704 slots (bounded in-kernel)
    fm_main_kernel<<<grid, 256>>>(x, out);
}

// round 2
// speedup vs baseline: 1.4040x; 1.4040x over previous
#include <cuda_runtime.h>
#include <cstdint>

// FMLayer: out[b, p] = wdot[p] * x[b, j1(p)] * x[b, j2(p)]
//   N_FEATURES = 512, K = 4, BATCH = 1024, P = 130816 (upper triangle, row-major by j1)
// DRAM-write-bound: 535.8 MB out per launch. Strategy: minimize L1 wavefronts/byte.

#define NF    512
#define KDIM  4
#define BATCH 1024
#define NPAIR 130816              // 512*511/2
#define NQ4   (NPAIR / 4)         // 32704 float4 slots per batch row
#define BT    4                   // batch rows per block (amortizes wdot/meta reads)

// Scratch (allocation-free rule: __device__ globals)
__device__ __align__(16) float g_wdot[NPAIR];
__device__ __align__(16) int   g_jidx[NPAIR];   // (j1 << 16) | j2  (per pair, slow path)
__device__ __align__(16) int   g_meta[NQ4];     // (j1 << 16) | j2start, or -1 if row-crossing

__device__ __forceinline__ int tri_offset(int j1) {
    return (NF - 1) * j1 - (j1 * (j1 - 1)) / 2;
}

__global__ void fm_setup_kernel(const float* __restrict__ w) {
    int p = blockIdx.x * blockDim.x + threadIdx.x;
    if (p >= NPAIR) return;

    double disc = 1023.0 * 1023.0 - 8.0 * (double)p;
    int j1 = (int)((1023.0 - sqrt(disc)) * 0.5);
    if (j1 < 0) j1 = 0;
    while (j1 + 1 < NF && tri_offset(j1 + 1) <= p) j1++;
    while (j1 > 0 && tri_offset(j1) > p) j1--;
    int j2 = p - tri_offset(j1) + j1 + 1;

    const float4* w4 = reinterpret_cast<const float4*>(w);
    float4 a = __ldg(&w4[j1]);
    float4 b = __ldg(&w4[j2]);
    g_wdot[p] = a.x * b.x + a.y * b.y + a.z * b.z + a.w * b.w;
    g_jidx[p] = (j1 << 16) | j2;
}

__global__ void fm_meta_kernel() {
    int q = blockIdx.x * blockDim.x + threadIdx.x;
    if (q >= NQ4) return;
    int j_first = g_jidx[4 * q];
    int j_last  = g_jidx[4 * q + 3];
    // same j1 for all 4 pairs? (high halves equal)
    if ((j_first >> 16) == (j_last >> 16))
        g_meta[q] = j_first;          // (j1<<16) | j2start
    else
        g_meta[q] = -1;               // row-crossing: slow path
}

// Block = (pair chunk of 1024 float4) x (4 batch rows). 256 threads, 4 q each.
// Shared: 4 shifted copies of each of the 4 x rows -> aligned LDS.128 for x[j2..j2+3].
__global__ void __launch_bounds__(256) fm_main_kernel(
    const float* __restrict__ x, float* __restrict__ out)
{
    __shared__ float xs[BT][4][NF];   // xs[b][a][i] = x_row_b[a + i]; 32 KB

    const int b0 = blockIdx.y * BT;

    // Fill shifted copies: one coalesced read of each x row, 4 shared writes.
    for (int i = threadIdx.x; i < BT * NF; i += 256) {
        int bb = i >> 9;              // / NF
        int j  = i & (NF - 1);
        float v = x[(size_t)(b0 + bb) * NF + j];
        #pragma unroll
        for (int a = 0; a < 4; a++)
            if (j >= a) xs[bb][a][j - a] = v;
    }
    __syncthreads();

    const int4*   jid4 = reinterpret_cast<const int4*>(g_jidx);
    const float4* wd4  = reinterpret_cast<const float4*>(g_wdot);

    const int qbase = blockIdx.x * 1024 + threadIdx.x;

    // Preload per-q metadata + wdot once (reused across BT batch rows).
    int    m[4];
    float4 wd[4];
    #pragma unroll
    for (int u = 0; u < 4; u++) {
        int q = qbase + u * 256;
        if (q < NQ4) {
            m[u]  = g_meta[q];
            wd[u] = wd4[q];
        } else {
            m[u] = 0; wd[u] = make_float4(0.f, 0.f, 0.f, 0.f);
        }
    }

    #pragma unroll
    for (int bb = 0; bb < BT; bb++) {
        float4* ob = reinterpret_cast<float4*>(out + (size_t)(b0 + bb) * NPAIR);
        #pragma unroll
        for (int u = 0; u < 4; u++) {
            int q = qbase + u * 256;
            if (q >= NQ4) continue;
            float4 r;
            int mu = m[u];
            if (mu >= 0) {
                // fast path: all 4 pairs share j1, j2 contiguous
                int j1  = mu >> 16;
                int j2s = mu & 0xffff;
                int a   = j2s & 3;
                float s = xs[bb][0][j1];
                float4 xv = reinterpret_cast<const float4*>(xs[bb][a])[(j2s - a) >> 2];
                float4 w4v = wd[u];
                r.x = s * w4v.x * xv.x;
                r.y = s * w4v.y * xv.y;
                r.z = s * w4v.z * xv.z;
                r.w = s * w4v.w * xv.w;
            } else {
                // slow path (1.6% of q): row-crossing, per-element gather
                int4 j = jid4[q];
                float4 w4v = wd[u];
                r.x = w4v.x * xs[bb][0][j.x >> 16] * xs[bb][0][j.x & 0xffff];
                r.y = w4v.y * xs[bb][0][j.y >> 16] * xs[bb][0][j.y & 0xffff];
                r.z = w4v.z * xs[bb][0][j.z >> 16] * xs[bb][0][j.z & 0xffff];
                r.w = w4v.w * xs[bb][0][j.w >> 16] * xs[bb][0][j.w & 0xffff];
            }
            __stcs(&ob[q], r);        // streaming store: output never re-read
        }
    }
}

extern "C" void kernel_launch(void* const* d_in, const int* in_sizes, int n_in,
                              void* d_out, int out_size)
{
    const float* x = (const float*)d_in[0];   // [1024, 512]
    const float* w = (const float*)d_in[1];   // [512, 4]
    float* out = (float*)d_out;               // [1024, 130816]
    (void)in_sizes; (void)n_in; (void)out_size;

    fm_setup_kernel<<<(NPAIR + 255) / 256, 256>>>(w);
    fm_meta_kernel<<<(NQ4 + 255) / 256, 256>>>();

    dim3 grid(32, BATCH / BT);   // 32 chunks * 1024 f4 = 32768 >= 32704 (guarded)
    fm_main_kernel<<<grid, 256>>>(x, out);
}